// round 6
// baseline (speedup 1.0000x reference)
#include <cuda_runtime.h>
#include <cuda_bf16.h>

// ---------------------------------------------------------------------------
// KAN feature extractor, GB300 sm_103a — fast closed-form basis version.
//   layer1: KANconv3x3 (1->2) on 28x28 + maxpool2 -> (B,2,14,14)
//   layer2: KANconv3x3 (2->2) on 14x14 + maxpool2 -> (B,2,7,7) -> (B,98)
//
// Uniform knots g[j] = (j-3)*0.4 - 1.0, j=0..11. For x in [g[i], g[i+1)),
// i in [0,10], exactly 4 cubic bases are nonzero (t = local param):
//   B_{i-3}=(1-t)^3/6, B_{i-2}=(3t^3-6t^2+4)/6,
//   B_{i-1}=(-3t^3+3t^2+3t+1)/6, B_i=t^3/6
// Outside [-2.2, 2.2) all bases are zero. Verified equivalent to the
// reference Cox-de Boor recursion (R1 vs R2 outputs identical).
// Shared weights are slot-major (slot = basis_index+3, slots 0-2 & 11-15
// zero) so boundary intervals need no branches.
// ---------------------------------------------------------------------------

#define MAX_B 4096
__device__ float g_mid[MAX_B * 2 * 14 * 14];   // intermediate (B,2,14,14)

__device__ __forceinline__ float silu_f(float v) {
    return __fdividef(v, 1.0f + __expf(-v));
}

__device__ __forceinline__ void bspline_w4(float x, int& i,
                                           float& b0, float& b1,
                                           float& b2, float& b3) {
    float u  = (x + 2.2f) * 2.5f;          // (x - g[0]) / h
    float fi = floorf(u);
    int   ii = (int)fi;
    float t  = u - fi;
    bool  inb = (ii >= 0) && (ii <= 10);
    if (!inb) { ii = 0; t = 0.0f; }
    float t2  = t * t;
    float t3  = t2 * t;
    float omt = 1.0f - t;
    const float c6 = 1.0f / 6.0f;
    b0 = omt * omt * omt * c6;
    b1 = (3.0f * t3 - 6.0f * t2 + 4.0f) * c6;
    b2 = (-3.0f * t3 + 3.0f * t2 + 3.0f * t + 1.0f) * c6;
    b3 = t3 * c6;
    if (!inb) { b0 = b1 = b2 = b3 = 0.0f; }
    i = ii;
}

// ---------------------------------------------------------------------------
// Layer 1: Cin=1, Cout=2. One thread per pooled cell (b,h2,w2).
// ---------------------------------------------------------------------------
#define S1 19
__global__ void __launch_bounds__(256)
kan_layer1(const float* __restrict__ x,        // (B,1,28,28)
           const float* __restrict__ base_w,   // (2,1,9)
           const float* __restrict__ spline_w, // (2,1,9,8)
           const float* __restrict__ scaler,   // (2,1,9)
           int B) {
    __shared__ float swsh[16 * S1];  // [slot][o*9+k]
    __shared__ float bwsh[18];       // [o*9+k]

    int tid = threadIdx.x;
    for (int idx = tid; idx < 16 * S1; idx += blockDim.x) swsh[idx] = 0.0f;
    __syncthreads();
    for (int idx = tid; idx < 144; idx += blockDim.x) {
        int g = idx & 7;
        int col = idx >> 3;               // o*9+k
        swsh[(g + 3) * S1 + col] = spline_w[idx] * scaler[col];
    }
    for (int idx = tid; idx < 18; idx += blockDim.x) bwsh[idx] = base_w[idx];
    __syncthreads();

    int t = blockIdx.x * blockDim.x + tid;
    if (t >= B * 196) return;
    int b   = t / 196;
    int rem = t - b * 196;
    int h2  = rem / 14;
    int w2  = rem - h2 * 14;

    const float* xb = x + b * 784;
    int h0 = 2 * h2 - 1;
    int w0 = 2 * w2 - 1;

    float val[4][4];
#pragma unroll
    for (int r = 0; r < 4; r++) {
        int  hh    = h0 + r;
        bool rowok = (hh >= 0) && (hh < 28);
#pragma unroll
        for (int c = 0; c < 4; c++) {
            int  ww = w0 + c;
            bool ok = rowok && (ww >= 0) && (ww < 28);
            val[r][c] = ok ? xb[hh * 28 + ww] : 0.0f;  // pad zeros are real inputs
        }
    }

    float acc[2][2][2];  // [dy][dx][o]
#pragma unroll
    for (int dy = 0; dy < 2; dy++)
#pragma unroll
        for (int dx = 0; dx < 2; dx++)
#pragma unroll
            for (int o = 0; o < 2; o++) acc[dy][dx][o] = 0.0f;

#pragma unroll
    for (int r = 0; r < 4; r++) {
#pragma unroll
        for (int c = 0; c < 4; c++) {
            float v = val[r][c];
            float s = silu_f(v);
            int   i;
            float b0, b1, b2, b3;
            bspline_w4(v, i, b0, b1, b2, b3);
            const float* sp0 = &swsh[i * S1];
#pragma unroll
            for (int dy = 0; dy < 2; dy++) {
                if (r - dy < 0 || r - dy > 2) continue;
#pragma unroll
                for (int dx = 0; dx < 2; dx++) {
                    if (c - dx < 0 || c - dx > 2) continue;
                    int k = (r - dy) * 3 + (c - dx);
#pragma unroll
                    for (int o = 0; o < 2; o++) {
                        const float* sp = sp0 + o * 9 + k;
                        float a = bwsh[o * 9 + k] * s;
                        a = fmaf(sp[0 * S1], b0, a);
                        a = fmaf(sp[1 * S1], b1, a);
                        a = fmaf(sp[2 * S1], b2, a);
                        a = fmaf(sp[3 * S1], b3, a);
                        acc[dy][dx][o] += a;
                    }
                }
            }
        }
    }

#pragma unroll
    for (int o = 0; o < 2; o++) {
        float m = fmaxf(fmaxf(acc[0][0][o], acc[0][1][o]),
                        fmaxf(acc[1][0][o], acc[1][1][o]));
        g_mid[b * 392 + o * 196 + h2 * 14 + w2] = m;
    }
}

// ---------------------------------------------------------------------------
// Layer 2: Cin=2, Cout=2 on 14x14. One thread per pooled cell.
// ---------------------------------------------------------------------------
#define S2 37
__global__ void __launch_bounds__(256)
kan_layer2(const float* __restrict__ base_w,   // (2,2,9)
           const float* __restrict__ spline_w, // (2,2,9,8)
           const float* __restrict__ scaler,   // (2,2,9)
           float* __restrict__ out,            // (B,98)
           int B) {
    __shared__ float swsh[16 * S2];  // [slot][o*18+ci*9+k]
    __shared__ float bwsh[36];

    int tid = threadIdx.x;
    for (int idx = tid; idx < 16 * S2; idx += blockDim.x) swsh[idx] = 0.0f;
    __syncthreads();
    for (int idx = tid; idx < 288; idx += blockDim.x) {   // FIX: loop, not if
        int g   = idx & 7;
        int col = idx >> 3;               // (o*2+ci)*9+k == o*18+ci*9+k
        swsh[(g + 3) * S2 + col] = spline_w[idx] * scaler[col];
    }
    for (int idx = tid; idx < 36; idx += blockDim.x) bwsh[idx] = base_w[idx];
    __syncthreads();

    int t = blockIdx.x * blockDim.x + tid;
    if (t >= B * 49) return;
    int b   = t / 49;
    int rem = t - b * 49;
    int h2  = rem / 7;
    int w2  = rem - h2 * 7;

    int h0 = 2 * h2 - 1;
    int w0 = 2 * w2 - 1;

    float acc[2][2][2];  // [dy][dx][o]
#pragma unroll
    for (int dy = 0; dy < 2; dy++)
#pragma unroll
        for (int dx = 0; dx < 2; dx++)
#pragma unroll
            for (int o = 0; o < 2; o++) acc[dy][dx][o] = 0.0f;

#pragma unroll
    for (int ci = 0; ci < 2; ci++) {
        const float* mb = g_mid + b * 392 + ci * 196;
        float val[4][4];
#pragma unroll
        for (int r = 0; r < 4; r++) {
            int  hh    = h0 + r;
            bool rowok = (hh >= 0) && (hh < 14);
#pragma unroll
            for (int c = 0; c < 4; c++) {
                int  ww = w0 + c;
                bool ok = rowok && (ww >= 0) && (ww < 14);
                val[r][c] = ok ? mb[hh * 14 + ww] : 0.0f;
            }
        }
#pragma unroll
        for (int r = 0; r < 4; r++) {
#pragma unroll
            for (int c = 0; c < 4; c++) {
                float v = val[r][c];
                float s = silu_f(v);
                int   i;
                float b0, b1, b2, b3;
                bspline_w4(v, i, b0, b1, b2, b3);
                const float* sp0 = &swsh[i * S2 + ci * 9];
#pragma unroll
                for (int dy = 0; dy < 2; dy++) {
                    if (r - dy < 0 || r - dy > 2) continue;
#pragma unroll
                    for (int dx = 0; dx < 2; dx++) {
                        if (c - dx < 0 || c - dx > 2) continue;
                        int k = (r - dy) * 3 + (c - dx);
#pragma unroll
                        for (int o = 0; o < 2; o++) {
                            const float* sp = sp0 + o * 18 + k;
                            float a = bwsh[o * 18 + ci * 9 + k] * s;
                            a = fmaf(sp[0 * S2], b0, a);
                            a = fmaf(sp[1 * S2], b1, a);
                            a = fmaf(sp[2 * S2], b2, a);
                            a = fmaf(sp[3 * S2], b3, a);
                            acc[dy][dx][o] += a;
                        }
                    }
                }
            }
        }
    }

#pragma unroll
    for (int o = 0; o < 2; o++) {
        float m = fmaxf(fmaxf(acc[0][0][o], acc[0][1][o]),
                        fmaxf(acc[1][0][o], acc[1][1][o]));
        out[b * 98 + o * 49 + h2 * 7 + w2] = m;
    }
}

extern "C" void kernel_launch(void* const* d_in, const int* in_sizes, int n_in,
                              void* d_out, int out_size) {
    // Size-based pointer resolution (robust to metadata ordering; base_w
    // precedes scaler in both dict and alphabetical order).
    const float *x = 0, *bw1 = 0, *sw1 = 0, *sc1 = 0, *bw2 = 0, *sw2 = 0, *sc2 = 0;
    if (n_in == 7) {
        for (int i = 0; i < n_in; i++) {
            int s = in_sizes[i];
            const float* p = (const float*)d_in[i];
            if      (s == 144) sw1 = p;
            else if (s == 288) sw2 = p;
            else if (s == 18)  { if (!bw1) bw1 = p; else sc1 = p; }
            else if (s == 36)  { if (!bw2) bw2 = p; else sc2 = p; }
            else               x = p;
        }
    }
    if (!x || !bw1 || !sw1 || !sc1 || !bw2 || !sw2 || !sc2) {
        x   = (const float*)d_in[0];
        bw1 = (const float*)d_in[1];
        sw1 = (const float*)d_in[2];
        sc1 = (const float*)d_in[3];
        bw2 = (const float*)d_in[4];
        sw2 = (const float*)d_in[5];
        sc2 = (const float*)d_in[6];
    }
    float* out = (float*)d_out;

    int B = out_size / 98;
    if (B > MAX_B) B = MAX_B;

    int n1 = B * 196;
    int n2 = B * 49;
    kan_layer1<<<(n1 + 255) / 256, 256>>>(x, bw1, sw1, sc1, B);
    kan_layer2<<<(n2 + 255) / 256, 256>>>(bw2, sw2, sc2, out, B);
}